// round 11
// baseline (speedup 1.0000x reference)
#include <cuda_runtime.h>
#include <math.h>

// ---------------------------------------------------------------------------
// ann2_snn1 — bit-exact emulation of the JAX/XLA fp32 reference, optimized.
//   h     = relu(inputs @ w1.T + b1)        k-sequential FFMA chains
//   drive = sigmoid(h @ w2.T + b2)          sigmoid = 0.5+0.5*tanh(0.5x), XLA tanh
//   scan: psp = a1*p1 + a2*p2 + drive       separate fp32 roundings
//         cur = psp @ w3.T + b3             k-sequential FFMA chains
//         v   = sigma*v*(1-s) + cur ; s = (v>=1)
// Head: producer/consumer pipelined over 8 k-chunks of 64 with double-buffered
// psp history; consumers do 2 timesteps x 5 outputs per thread (reg-blocked).
// ---------------------------------------------------------------------------

#define BM 64
#define BN 64
#define BK 32

#define BATCH 1024
#define H1 500
#define H2 500
#define NIN 784
#define NOUT 10
#define TSTEPS 100

#define HT 512              // head threads
#define HROW2 68            // hist row stride (17 float4, odd -> conflict-free)
#define KCH 64              // k-chunk
#define NCH 8               // chunks: 7*64 + 52 = 500

// scratch (no cudaMalloc allowed)
__device__ float g_h[BATCH * H1];
__device__ float g_drive[BATCH * H2];

// XLA F32 tanh rational approximation (matches reference bit-for-bit).
__device__ __forceinline__ float xla_tanh_f32(float x)
{
    const float kMax = 7.90531110763549805f;
    float ax = fabsf(x);
    float xc = fminf(fmaxf(x, -kMax), kMax);
    float x2 = __fmul_rn(xc, xc);

    float np = -2.76076847742355e-16f;
    np = fmaf(np, x2, 2.00018790482477e-13f);
    np = fmaf(np, x2, -8.60467152213735e-11f);
    np = fmaf(np, x2, 5.12229709037114e-08f);
    np = fmaf(np, x2, 1.48572235717979e-05f);
    np = fmaf(np, x2, 6.37261928875436e-04f);
    np = fmaf(np, x2, 4.89352455891786e-03f);
    float num = __fmul_rn(xc, np);

    float dp = 1.19825839466702e-06f;
    dp = fmaf(dp, x2, 1.18534705686654e-04f);
    dp = fmaf(dp, x2, 2.26843463243900e-03f);
    dp = fmaf(dp, x2, 4.89352518554385e-03f);

    float r = __fdiv_rn(num, dp);
    return (ax < 0.0004f) ? x : r;
}

__device__ __forceinline__ float4 ld4_guard(const float* row, int k, int K)
{
    if (k + 4 <= K)
        return *reinterpret_cast<const float4*>(row + k);
    float4 v;
    v.x = (k + 0 < K) ? row[k + 0] : 0.f;
    v.y = (k + 1 < K) ? row[k + 1] : 0.f;
    v.z = (k + 2 < K) ? row[k + 2] : 0.f;
    v.w = (k + 3 < K) ? row[k + 3] : 0.f;
    return v;
}

// C[M,N] = act(A[M,K] @ B[N,K]^T + bias[N]); ACT 0=relu, 1=xla-sigmoid.
// Double-buffered smem, register prefetch, ONE sync per 32-wide K-tile.
// Strictly k-ascending single-acc fmaf per output element (bit-exact).
template <int ACT>
__global__ __launch_bounds__(256)
void gemm_bias_act(const float* __restrict__ A, const float* __restrict__ B,
                   const float* __restrict__ bias, float* __restrict__ C,
                   int M, int N, int K)
{
    __shared__ float As[2][BK][BM];
    __shared__ float Bs[2][BK][BN];

    const int tid = threadIdx.x;
    const int lr  = tid >> 2;
    const int kq  = (tid & 3) << 2;
    const int ty  = tid >> 4;
    const int tx  = tid & 15;

    const int gm = blockIdx.y * BM + lr;
    const int gn = blockIdx.x * BN + lr;

    const float* Arow = A + (size_t)gm * K;
    const float* Brow = B + (size_t)gn * K;
    const bool bn_ok  = (gn < N);

    const int nIter = (K + BK - 1) / BK;

    {
        float4 a0 = ld4_guard(Arow, kq, K);
        float4 a1 = ld4_guard(Arow, kq + 16, K);
        float4 b0 = bn_ok ? ld4_guard(Brow, kq, K)      : make_float4(0,0,0,0);
        float4 b1 = bn_ok ? ld4_guard(Brow, kq + 16, K) : make_float4(0,0,0,0);
        As[0][kq + 0][lr] = a0.x; As[0][kq + 1][lr] = a0.y;
        As[0][kq + 2][lr] = a0.z; As[0][kq + 3][lr] = a0.w;
        As[0][kq + 16][lr] = a1.x; As[0][kq + 17][lr] = a1.y;
        As[0][kq + 18][lr] = a1.z; As[0][kq + 19][lr] = a1.w;
        Bs[0][kq + 0][lr] = b0.x; Bs[0][kq + 1][lr] = b0.y;
        Bs[0][kq + 2][lr] = b0.z; Bs[0][kq + 3][lr] = b0.w;
        Bs[0][kq + 16][lr] = b1.x; Bs[0][kq + 17][lr] = b1.y;
        Bs[0][kq + 18][lr] = b1.z; Bs[0][kq + 19][lr] = b1.w;
    }
    __syncthreads();

    float acc[4][4] = {};
    int buf = 0;

    for (int it = 0; it < nIter; ++it) {
        float4 a0, a1, b0, b1;
        const bool more = (it + 1 < nIter);
        if (more) {
            const int ka = (it + 1) * BK + kq;
            a0 = ld4_guard(Arow, ka, K);
            a1 = ld4_guard(Arow, ka + 16, K);
            b0 = bn_ok ? ld4_guard(Brow, ka, K)      : make_float4(0,0,0,0);
            b1 = bn_ok ? ld4_guard(Brow, ka + 16, K) : make_float4(0,0,0,0);
        }

        #pragma unroll
        for (int kk = 0; kk < BK; kk++) {
            float4 a = *reinterpret_cast<const float4*>(&As[buf][kk][ty << 2]);
            float4 b = *reinterpret_cast<const float4*>(&Bs[buf][kk][tx << 2]);
            float ar[4] = {a.x, a.y, a.z, a.w};
            float br[4] = {b.x, b.y, b.z, b.w};
            #pragma unroll
            for (int i = 0; i < 4; i++)
                #pragma unroll
                for (int j = 0; j < 4; j++)
                    acc[i][j] = fmaf(ar[i], br[j], acc[i][j]);
        }

        if (more) {
            const int nb = buf ^ 1;
            As[nb][kq + 0][lr] = a0.x; As[nb][kq + 1][lr] = a0.y;
            As[nb][kq + 2][lr] = a0.z; As[nb][kq + 3][lr] = a0.w;
            As[nb][kq + 16][lr] = a1.x; As[nb][kq + 17][lr] = a1.y;
            As[nb][kq + 18][lr] = a1.z; As[nb][kq + 19][lr] = a1.w;
            Bs[nb][kq + 0][lr] = b0.x; Bs[nb][kq + 1][lr] = b0.y;
            Bs[nb][kq + 2][lr] = b0.z; Bs[nb][kq + 3][lr] = b0.w;
            Bs[nb][kq + 16][lr] = b1.x; Bs[nb][kq + 17][lr] = b1.y;
            Bs[nb][kq + 18][lr] = b1.z; Bs[nb][kq + 19][lr] = b1.w;
        }
        __syncthreads();
        buf ^= 1;
    }

    const int om = blockIdx.y * BM + (ty << 2);
    const int on = blockIdx.x * BN + (tx << 2);
    #pragma unroll
    for (int j = 0; j < 4; j++) {
        const int n = on + j;
        if (n >= N) continue;
        const float bb = bias[n];
        #pragma unroll
        for (int i = 0; i < 4; i++) {
            float z = __fadd_rn(acc[i][j], bb);
            float v;
            if (ACT == 0) {
                v = fmaxf(z, 0.f);
            } else {
                float th = xla_tanh_f32(__fmul_rn(0.5f, z));
                v = __fadd_rn(0.5f, __fmul_rn(0.5f, th));
            }
            C[(size_t)(om + i) * N + n] = v;
        }
    }
}

// psp recurrence for one synapse k into hist row-major [t][HROW2] (exact
// reference roundings).
__device__ __forceinline__ void produce_psp(float* __restrict__ hb, float d,
                                            int kk, float a1, float a2)
{
    float p1 = 0.f, p2 = 0.f;
    #pragma unroll 4
    for (int tt = 0; tt < TSTEPS; ++tt) {
        float ps = __fadd_rn(__fadd_rn(__fmul_rn(a1, p1), __fmul_rn(a2, p2)), d);
        hb[tt * HROW2 + kk] = ps;
        p2 = p1;
        p1 = ps;
    }
}

// Head: one block per batch row. Pipelined: producer warps (tid 128..191)
// compute psp chunk c+1 while consumers (tid<100) run the GEMV on chunk c.
// Consumer owns timesteps {t0, t0+50} x outputs {5*oq..5*oq+4}: 10 register
// accumulators, each a single strictly k-ascending fmaf chain (bit-exact).
__global__ __launch_bounds__(HT, 2)
void snn_head(const float* __restrict__ drive, const float* __restrict__ w3,
              const float* __restrict__ b3, float* __restrict__ out,
              float a1, float a2, float sigma)
{
    extern __shared__ float sm[];
    float* hist0 = sm;                          // [100][68]
    float* hist1 = sm + TSTEPS * HROW2;         // [100][68]
    float* w3s   = sm + 2 * TSTEPS * HROW2;     // [10][500] = 5000
    float* curs  = w3s + NOUT * H2;             // [100][10]
    float* spk   = curs + TSTEPS * NOUT;        // [10][100]

    const int b   = blockIdx.x;
    const int tid = threadIdx.x;

    for (int i = tid; i < NOUT * H2; i += HT)
        w3s[i] = w3[i];

    const bool prod = (tid >= 128 && tid < 128 + KCH);
    const int  pk   = tid - 128;

    // prologue: chunk 0 -> hist0
    if (prod)
        produce_psp(hist0, drive[(size_t)b * H2 + pk], pk, a1, a2);
    __syncthreads();

    const int t0 = tid % 50;       // consumer (tid<100)
    const int oq = tid / 50;       // 0 or 1
    float acA[5] = {0.f, 0.f, 0.f, 0.f, 0.f};
    float acB[5] = {0.f, 0.f, 0.f, 0.f, 0.f};

    for (int c = 0; c < NCH; ++c) {
        float* rd = (c & 1) ? hist1 : hist0;
        float* wr = (c & 1) ? hist0 : hist1;

        // producer: chunk c+1
        if (prod && (c + 1 < NCH)) {
            const int kg   = (c + 1) * KCH + pk;
            const int nlen = (c + 2 < NCH) ? KCH : (H2 - (NCH - 1) * KCH);
            if (pk < ((c + 1 < NCH - 1) ? KCH : nlen) && kg < H2)
                produce_psp(wr, drive[(size_t)b * H2 + kg], pk, a1, a2);
        }

        // consumer: chunk c
        if (tid < 100) {
            const int k0   = c * KCH;
            const int klen = (c < NCH - 1) ? KCH : (H2 - (NCH - 1) * KCH);
            const int nq   = klen >> 2;
            const float4* h4 = reinterpret_cast<const float4*>(rd);
            const float4* w4 = reinterpret_cast<const float4*>(w3s);
            const int hA = t0 * (HROW2 / 4);
            const int hB = (t0 + 50) * (HROW2 / 4);
            const int wb = (oq * 5) * (H2 / 4) + (k0 >> 2);
            #pragma unroll 4
            for (int j = 0; j < nq; ++j) {
                float4 ha = h4[hA + j];
                float4 hb = h4[hB + j];
                #pragma unroll
                for (int o = 0; o < 5; ++o) {
                    float4 w = w4[wb + o * (H2 / 4) + j];
                    float aA = acA[o];
                    aA = fmaf(ha.x, w.x, aA);
                    aA = fmaf(ha.y, w.y, aA);
                    aA = fmaf(ha.z, w.z, aA);
                    aA = fmaf(ha.w, w.w, aA);
                    acA[o] = aA;
                    float aB = acB[o];
                    aB = fmaf(hb.x, w.x, aB);
                    aB = fmaf(hb.y, w.y, aB);
                    aB = fmaf(hb.z, w.z, aB);
                    aB = fmaf(hb.w, w.w, aB);
                    acB[o] = aB;
                }
            }
        }
        __syncthreads();
    }

    if (tid < 100) {
        #pragma unroll
        for (int o = 0; o < 5; ++o) {
            curs[t0 * NOUT + oq * 5 + o]        = __fadd_rn(acA[o], b3[oq * 5 + o]);
            curs[(t0 + 50) * NOUT + oq * 5 + o] = __fadd_rn(acB[o], b3[oq * 5 + o]);
        }
    }
    __syncthreads();

    // membrane scan (separate roundings), spikes to smem in [o][t] layout
    if (tid < NOUT) {
        float v = 0.f, s = 0.f;
        #pragma unroll 4
        for (int tt = 0; tt < TSTEPS; ++tt) {
            float m = __fmul_rn(__fmul_rn(sigma, v), __fsub_rn(1.0f, s));
            v = __fadd_rn(m, curs[tt * NOUT + tid]);
            s = (v >= 1.0f) ? 1.0f : 0.0f;
            spk[tid * TSTEPS + tt] = s;
        }
    }
    __syncthreads();

    // coalesced writeback: 1000 contiguous floats per block
    float4* o4 = reinterpret_cast<float4*>(out + (size_t)b * NOUT * TSTEPS);
    const float4* s4 = reinterpret_cast<const float4*>(spk);
    if (tid < NOUT * TSTEPS / 4)
        o4[tid] = s4[tid];
}

extern "C" void kernel_launch(void* const* d_in, const int* in_sizes, int n_in,
                              void* d_out, int out_size)
{
    const float* inputs = (const float*)d_in[0];  // [1024, 784]
    const float* w1     = (const float*)d_in[1];  // [500, 784]
    const float* b1     = (const float*)d_in[2];  // [500]
    const float* w2     = (const float*)d_in[3];  // [500, 500]
    const float* b2     = (const float*)d_in[4];  // [500]
    const float* w3     = (const float*)d_in[5];  // [10, 500]
    const float* b3     = (const float*)d_in[6];  // [10]
    float* out          = (float*)d_out;          // [1024, 10, 100]

    float *h = nullptr, *drive = nullptr;
    cudaGetSymbolAddress((void**)&h, g_h);
    cudaGetSymbolAddress((void**)&drive, g_drive);

    const double em = exp(-1.0 / 4.0);
    const double es = exp(-1.0 / 1.0);
    const float a1f = (float)(em + es);
    const float a2f = (float)(-em * es);
    const float sgf = (float)em;

    dim3 blk(256);
    dim3 g1((H1 + BN - 1) / BN, (BATCH + BM - 1) / BM);   // (8, 16)
    gemm_bias_act<0><<<g1, blk>>>(inputs, w1, b1, h, BATCH, H1, NIN);
    gemm_bias_act<1><<<g1, blk>>>(h, w2, b2, drive, BATCH, H2, H1);

    const int head_smem =
        (2 * TSTEPS * HROW2 + NOUT * H2 + 2 * TSTEPS * NOUT) * sizeof(float);
    cudaFuncSetAttribute(snn_head, cudaFuncAttributeMaxDynamicSharedMemorySize,
                         head_smem);
    snn_head<<<BATCH, HT, head_smem>>>(drive, w3, b3, out, a1f, a2f, sgf);
}

// round 16
// speedup vs baseline: 1.0970x; 1.0970x over previous
#include <cuda_runtime.h>
#include <math.h>

// ---------------------------------------------------------------------------
// ann2_snn1 — bit-exact emulation of the JAX/XLA fp32 reference, optimized.
//   h     = relu(inputs @ w1.T + b1)        k-sequential FFMA chains
//   drive = sigmoid(h @ w2.T + b2)          sigmoid = 0.5+0.5*tanh(0.5x), XLA tanh
//   scan: psp = a1*p1 + a2*p2 + drive       separate fp32 roundings
//         cur = psp @ w3.T + b3             k-sequential FFMA chains
//         v   = sigma*v*(1-s) + cur ; s = (v>=1)
// R12: GEMM retiled 32x64/128thr (grid 256, all SMs). Head: 4 rows/block,
// 1 block/SM (196KB smem), 5 k-chunks of 100, 400 worker threads that both
// produce psp and consume 10 reg-resident fmaf chains each.
// ---------------------------------------------------------------------------

#define BM 32
#define BN 64
#define BK 32

#define BATCH 1024
#define H1 500
#define H2 500
#define NIN 784
#define NOUT 10
#define TSTEPS 100

#define HT 512              // head threads
#define ROWS 4              // batch rows per head block
#define KC 100              // k-chunk (5 * 100 = 500, no tail)
#define NCHK 5

// scratch (no cudaMalloc allowed)
__device__ float g_h[BATCH * H1];
__device__ float g_drive[BATCH * H2];

// XLA F32 tanh rational approximation (matches reference bit-for-bit).
__device__ __forceinline__ float xla_tanh_f32(float x)
{
    const float kMax = 7.90531110763549805f;
    float ax = fabsf(x);
    float xc = fminf(fmaxf(x, -kMax), kMax);
    float x2 = __fmul_rn(xc, xc);

    float np = -2.76076847742355e-16f;
    np = fmaf(np, x2, 2.00018790482477e-13f);
    np = fmaf(np, x2, -8.60467152213735e-11f);
    np = fmaf(np, x2, 5.12229709037114e-08f);
    np = fmaf(np, x2, 1.48572235717979e-05f);
    np = fmaf(np, x2, 6.37261928875436e-04f);
    np = fmaf(np, x2, 4.89352455891786e-03f);
    float num = __fmul_rn(xc, np);

    float dp = 1.19825839466702e-06f;
    dp = fmaf(dp, x2, 1.18534705686654e-04f);
    dp = fmaf(dp, x2, 2.26843463243900e-03f);
    dp = fmaf(dp, x2, 4.89352518554385e-03f);

    float r = __fdiv_rn(num, dp);
    return (ax < 0.0004f) ? x : r;
}

__device__ __forceinline__ float4 ld4_guard(const float* row, int k, int K)
{
    if (k + 4 <= K)
        return *reinterpret_cast<const float4*>(row + k);
    float4 v;
    v.x = (k + 0 < K) ? row[k + 0] : 0.f;
    v.y = (k + 1 < K) ? row[k + 1] : 0.f;
    v.z = (k + 2 < K) ? row[k + 2] : 0.f;
    v.w = (k + 3 < K) ? row[k + 3] : 0.f;
    return v;
}

// C[M,N] = act(A[M,K] @ B[N,K]^T + bias[N]); ACT 0=relu, 1=xla-sigmoid.
// 32x64 tile, 128 threads (4x4 thread-tile), double-buffered, 1 sync/K-tile.
// Strictly k-ascending single-acc fmaf per element; zero-padded tail is an
// exact no-op -> bit-exact.
template <int ACT>
__global__ __launch_bounds__(128)
void gemm_bias_act(const float* __restrict__ A, const float* __restrict__ B,
                   const float* __restrict__ bias, float* __restrict__ C,
                   int M, int N, int K)
{
    __shared__ float As[2][BK][BM];
    __shared__ float Bs[2][BK][BN];

    const int tid = threadIdx.x;
    // A loader: 32 rows, 2 float4 each (k at kqA, kqA+16)
    const int lrA = tid >> 2;           // 0..31
    const int kqA = (tid & 3) << 2;     // 0,4,8,12
    // B loader: 64 rows, 4 float4 each (k at kqB, +8, +16, +24)
    const int lrB = tid >> 1;           // 0..63
    const int kqB = (tid & 1) << 2;     // 0,4
    // compute map: 8x16 threads, 4x4 tile
    const int ty  = tid >> 4;           // 0..7  -> rows ty*4..+3
    const int tx  = tid & 15;           // 0..15 -> cols tx*4..+3

    const int gm = blockIdx.y * BM + lrA;   // M=1024 always valid
    const int gn = blockIdx.x * BN + lrB;   // may exceed N

    const float* Arow = A + (size_t)gm * K;
    const float* Brow = B + (size_t)gn * K;
    const bool bn_ok  = (gn < N);

    const int nIter = (K + BK - 1) / BK;

    // prologue: tile 0 -> buf 0
    {
        float4 a0 = ld4_guard(Arow, kqA, K);
        float4 a1 = ld4_guard(Arow, kqA + 16, K);
        As[0][kqA + 0][lrA] = a0.x; As[0][kqA + 1][lrA] = a0.y;
        As[0][kqA + 2][lrA] = a0.z; As[0][kqA + 3][lrA] = a0.w;
        As[0][kqA + 16][lrA] = a1.x; As[0][kqA + 17][lrA] = a1.y;
        As[0][kqA + 18][lrA] = a1.z; As[0][kqA + 19][lrA] = a1.w;
        #pragma unroll
        for (int q = 0; q < 4; q++) {
            const int kb = kqB + q * 8;
            float4 bv = bn_ok ? ld4_guard(Brow, kb, K) : make_float4(0,0,0,0);
            Bs[0][kb + 0][lrB] = bv.x; Bs[0][kb + 1][lrB] = bv.y;
            Bs[0][kb + 2][lrB] = bv.z; Bs[0][kb + 3][lrB] = bv.w;
        }
    }
    __syncthreads();

    float acc[4][4] = {};
    int buf = 0;

    for (int it = 0; it < nIter; ++it) {
        float4 a0, a1, bv[4];
        const bool more = (it + 1 < nIter);
        if (more) {
            const int ka = (it + 1) * BK;
            a0 = ld4_guard(Arow, ka + kqA, K);
            a1 = ld4_guard(Arow, ka + kqA + 16, K);
            #pragma unroll
            for (int q = 0; q < 4; q++)
                bv[q] = bn_ok ? ld4_guard(Brow, ka + kqB + q * 8, K)
                              : make_float4(0,0,0,0);
        }

        #pragma unroll
        for (int kk = 0; kk < BK; kk++) {             // k ascending
            float4 a = *reinterpret_cast<const float4*>(&As[buf][kk][ty << 2]);
            float4 b = *reinterpret_cast<const float4*>(&Bs[buf][kk][tx << 2]);
            float ar[4] = {a.x, a.y, a.z, a.w};
            float br[4] = {b.x, b.y, b.z, b.w};
            #pragma unroll
            for (int i = 0; i < 4; i++)
                #pragma unroll
                for (int j = 0; j < 4; j++)
                    acc[i][j] = fmaf(ar[i], br[j], acc[i][j]);
        }

        if (more) {
            const int nb = buf ^ 1;
            As[nb][kqA + 0][lrA] = a0.x; As[nb][kqA + 1][lrA] = a0.y;
            As[nb][kqA + 2][lrA] = a0.z; As[nb][kqA + 3][lrA] = a0.w;
            As[nb][kqA + 16][lrA] = a1.x; As[nb][kqA + 17][lrA] = a1.y;
            As[nb][kqA + 18][lrA] = a1.z; As[nb][kqA + 19][lrA] = a1.w;
            #pragma unroll
            for (int q = 0; q < 4; q++) {
                const int kb = kqB + q * 8;
                Bs[nb][kb + 0][lrB] = bv[q].x; Bs[nb][kb + 1][lrB] = bv[q].y;
                Bs[nb][kb + 2][lrB] = bv[q].z; Bs[nb][kb + 3][lrB] = bv[q].w;
            }
        }
        __syncthreads();
        buf ^= 1;
    }

    const int om = blockIdx.y * BM + (ty << 2);
    const int on = blockIdx.x * BN + (tx << 2);
    #pragma unroll
    for (int j = 0; j < 4; j++) {
        const int n = on + j;
        if (n >= N) continue;
        const float bb = bias[n];
        #pragma unroll
        for (int i = 0; i < 4; i++) {
            float z = __fadd_rn(acc[i][j], bb);
            float v;
            if (ACT == 0) {
                v = fmaxf(z, 0.f);
            } else {
                float th = xla_tanh_f32(__fmul_rn(0.5f, z));
                v = __fadd_rn(0.5f, __fmul_rn(0.5f, th));
            }
            C[(size_t)(om + i) * N + n] = v;
        }
    }
}

// Head: 4 batch rows per block, 512 threads, ONE block per SM (196KB smem).
// 5 k-chunks of 100. 400 worker threads: each produces the psp recurrence for
// one (row, k) lane (exact reference roundings), then consumes as
// (row, t0 & t0+50, outputs oq*5..+4): 10 register accumulator chains, each a
// single strictly k-ascending fmaf chain across all 5 chunks (bit-exact).
// hist rows are 100 floats (25 float4, odd stride -> conflict-free LDS.128).
__global__ __launch_bounds__(HT, 1)
void snn_head(const float* __restrict__ drive, const float* __restrict__ w3,
              const float* __restrict__ b3, float* __restrict__ out,
              float a1, float a2, float sigma)
{
    extern __shared__ float sm[];
    float* hist = sm;                       // [ROWS][100][KC] = 40000 (160KB)
    float* w3s  = sm + ROWS * TSTEPS * KC;  // [10][500] = 5000
    float* curs = w3s + NOUT * H2;          // [ROWS][100][10] = 4000

    const int b0  = blockIdx.x * ROWS;
    const int tid = threadIdx.x;

    for (int i = tid; i < NOUT * H2; i += HT)
        w3s[i] = w3[i];

    const int wrow = tid / 100;       // worker row (tid < 400)
    const int wr   = tid % 100;
    const int oq   = wr / 50;         // 0,1 -> outputs oq*5..oq*5+4
    const int t0   = wr % 50;         // owns timesteps t0 and t0+50
    float acc[10] = {0.f,0.f,0.f,0.f,0.f,0.f,0.f,0.f,0.f,0.f};

    for (int c = 0; c < NCHK; ++c) {
        // Phase 1: psp recurrence, k = c*100 + wr for row wrow
        if (tid < 400) {
            const float d = drive[(size_t)(b0 + wrow) * H2 + c * KC + wr];
            float* hb = hist + wrow * (TSTEPS * KC) + wr;
            float p1 = 0.f, p2 = 0.f;
            #pragma unroll 4
            for (int tt = 0; tt < TSTEPS; ++tt) {
                float ps = __fadd_rn(
                    __fadd_rn(__fmul_rn(a1, p1), __fmul_rn(a2, p2)), d);
                hb[tt * KC] = ps;
                p2 = p1;
                p1 = ps;
            }
        }
        __syncthreads();

        // Phase 2: continue 10 k-ascending fmaf chains
        if (tid < 400) {
            const float4* h4 = reinterpret_cast<const float4*>(
                hist + wrow * (TSTEPS * KC));
            const float4* w4 = reinterpret_cast<const float4*>(w3s);
            const int hA = t0 * (KC / 4);
            const int hB = (t0 + 50) * (KC / 4);
            const int wb = (oq * 5) * (H2 / 4) + c * (KC / 4);
            #pragma unroll 5
            for (int j = 0; j < KC / 4; ++j) {
                float4 ha = h4[hA + j];
                float4 hb = h4[hB + j];
                #pragma unroll
                for (int o = 0; o < 5; ++o) {
                    float4 w = w4[wb + o * (H2 / 4) + j];
                    float aA = acc[o];
                    aA = fmaf(ha.x, w.x, aA);
                    aA = fmaf(ha.y, w.y, aA);
                    aA = fmaf(ha.z, w.z, aA);
                    aA = fmaf(ha.w, w.w, aA);
                    acc[o] = aA;
                    float aB = acc[5 + o];
                    aB = fmaf(hb.x, w.x, aB);
                    aB = fmaf(hb.y, w.y, aB);
                    aB = fmaf(hb.z, w.z, aB);
                    aB = fmaf(hb.w, w.w, aB);
                    acc[5 + o] = aB;
                }
            }
        }
        __syncthreads();   // hist reused next chunk
    }

    if (tid < 400) {
        #pragma unroll
        for (int o = 0; o < 5; ++o) {
            curs[wrow * 1000 + t0 * NOUT + oq * 5 + o] =
                __fadd_rn(acc[o], b3[oq * 5 + o]);
            curs[wrow * 1000 + (t0 + 50) * NOUT + oq * 5 + o] =
                __fadd_rn(acc[5 + o], b3[oq * 5 + o]);
        }
    }
    __syncthreads();

    // membrane scan (separate roundings); spikes into hist space (now free)
    float* spk = hist;                      // [ROWS][NOUT][TSTEPS]
    if (tid < ROWS * NOUT) {
        const int row = tid / NOUT;
        const int o   = tid % NOUT;
        float v = 0.f, s = 0.f;
        #pragma unroll 4
        for (int tt = 0; tt < TSTEPS; ++tt) {
            float m = __fmul_rn(__fmul_rn(sigma, v), __fsub_rn(1.0f, s));
            v = __fadd_rn(m, curs[row * 1000 + tt * NOUT + o]);
            s = (v >= 1.0f) ? 1.0f : 0.0f;
            spk[row * 1000 + o * TSTEPS + tt] = s;
        }
    }
    __syncthreads();

    // coalesced writeback: 4000 contiguous floats (rows b0..b0+3)
    float4* o4 = reinterpret_cast<float4*>(out + (size_t)b0 * NOUT * TSTEPS);
    const float4* s4 = reinterpret_cast<const float4*>(spk);
    for (int i = tid; i < ROWS * NOUT * TSTEPS / 4; i += HT)
        o4[i] = s4[i];
}

extern "C" void kernel_launch(void* const* d_in, const int* in_sizes, int n_in,
                              void* d_out, int out_size)
{
    const float* inputs = (const float*)d_in[0];  // [1024, 784]
    const float* w1     = (const float*)d_in[1];  // [500, 784]
    const float* b1     = (const float*)d_in[2];  // [500]
    const float* w2     = (const float*)d_in[3];  // [500, 500]
    const float* b2     = (const float*)d_in[4];  // [500]
    const float* w3     = (const float*)d_in[5];  // [10, 500]
    const float* b3     = (const float*)d_in[6];  // [10]
    float* out          = (float*)d_out;          // [1024, 10, 100]

    float *h = nullptr, *drive = nullptr;
    cudaGetSymbolAddress((void**)&h, g_h);
    cudaGetSymbolAddress((void**)&drive, g_drive);

    const double em = exp(-1.0 / 4.0);
    const double es = exp(-1.0 / 1.0);
    const float a1f = (float)(em + es);
    const float a2f = (float)(-em * es);
    const float sgf = (float)em;

    dim3 blk(128);
    dim3 g1((H1 + BN - 1) / BN, (BATCH + BM - 1) / BM);   // (8, 32) = 256
    gemm_bias_act<0><<<g1, blk>>>(inputs, w1, b1, h, BATCH, H1, NIN);
    gemm_bias_act<1><<<g1, blk>>>(h, w2, b2, drive, BATCH, H2, H1);

    const int head_smem =
        (ROWS * TSTEPS * KC + NOUT * H2 + ROWS * TSTEPS * NOUT) * sizeof(float);
    cudaFuncSetAttribute(snn_head, cudaFuncAttributeMaxDynamicSharedMemorySize,
                         head_smem);
    snn_head<<<BATCH / ROWS, HT, head_smem>>>(drive, w3, b3, out,
                                              a1f, a2f, sgf);
}